// round 14
// baseline (speedup 1.0000x reference)
#include <cuda_runtime.h>
#include <cuda_fp16.h>

#define NN 50000
#define EE 800000
#define IN_F 128
#define HID 64
#define OUT_F 40
#define NLAYER 3

// ---- scratch (device globals: no allocation allowed) ----
__device__ __align__(16) float  g_h[NN * HID];    // layer activations (fp32)
__device__ __align__(16) __half g_hws[NN * HID];  // dinv-prescaled conv output (fp16 gather payload)
__device__ __align__(16) float  g_r[NN * HID];    // residual path output (fp32)
__device__ float g_dinv[NN];
__device__ int   g_cnt[NN];
__device__ int   g_start[NN];
__device__ int   g_fill[NN];
__device__ int   g_srcbuf[EE];
__device__ int   g_total;

// ---- mma.sync m16n8k16 row.col f32.f16.f16.f32 (base sm_80+ PTX) ----
__device__ __forceinline__ void mma16816(float (&c)[4],
                                         unsigned a0, unsigned a1,
                                         unsigned a2, unsigned a3,
                                         unsigned b0, unsigned b1) {
    asm volatile(
        "mma.sync.aligned.m16n8k16.row.col.f32.f16.f16.f32 "
        "{%0,%1,%2,%3}, {%4,%5,%6,%7}, {%8,%9}, {%0,%1,%2,%3};\n"
        : "+f"(c[0]), "+f"(c[1]), "+f"(c[2]), "+f"(c[3])
        : "r"(a0), "r"(a1), "r"(a2), "r"(a3), "r"(b0), "r"(b1));
}

// ------------------------------------------------------------------
// CSR build (unordered segments: starts assigned by atomic bump)
// 8 edges/thread for MLP on the atomic/scatter path
// ------------------------------------------------------------------
__global__ void count_deg_k(const int* __restrict__ ei) {
    if (blockIdx.x == 0 && threadIdx.x == 0) g_total = 0;
    int e0 = (blockIdx.x * 256 + threadIdx.x) * 8;
    if (e0 < EE) {
        int4 da = *(const int4*)&ei[EE + e0];
        int4 db = *(const int4*)&ei[EE + e0 + 4];
        atomicAdd(&g_cnt[da.x], 1);
        atomicAdd(&g_cnt[da.y], 1);
        atomicAdd(&g_cnt[da.z], 1);
        atomicAdd(&g_cnt[da.w], 1);
        atomicAdd(&g_cnt[db.x], 1);
        atomicAdd(&g_cnt[db.y], 1);
        atomicAdd(&g_cnt[db.z], 1);
        atomicAdd(&g_cnt[db.w], 1);
    }
}

__global__ void start_k() {
    int i = blockIdx.x * 256 + threadIdx.x;
    if (i < NN) {
        int c = g_cnt[i];
        g_dinv[i] = rsqrtf((float)c + 1.0f);
        int s = atomicAdd(&g_total, c);
        g_start[i] = s;
        g_fill[i]  = s;
    }
}

__global__ void fill_k(const int* __restrict__ ei) {
    int e0 = (blockIdx.x * 256 + threadIdx.x) * 8;
    if (e0 < EE) {
        int4 sa = *(const int4*)&ei[e0];
        int4 sb = *(const int4*)&ei[e0 + 4];
        int4 da = *(const int4*)&ei[EE + e0];
        int4 db = *(const int4*)&ei[EE + e0 + 4];
        int p0 = atomicAdd(&g_fill[da.x], 1);
        int p1 = atomicAdd(&g_fill[da.y], 1);
        int p2 = atomicAdd(&g_fill[da.z], 1);
        int p3 = atomicAdd(&g_fill[da.w], 1);
        int p4 = atomicAdd(&g_fill[db.x], 1);
        int p5 = atomicAdd(&g_fill[db.y], 1);
        int p6 = atomicAdd(&g_fill[db.z], 1);
        int p7 = atomicAdd(&g_fill[db.w], 1);
        g_srcbuf[p0] = sa.x;
        g_srcbuf[p1] = sa.y;
        g_srcbuf[p2] = sa.z;
        g_srcbuf[p3] = sa.w;
        g_srcbuf[p4] = sb.x;
        g_srcbuf[p5] = sb.y;
        g_srcbuf[p6] = sb.z;
        g_srcbuf[p7] = sb.w;
    }
}

// ------------------------------------------------------------------
// former1 (mma): h = x @ Wf + bf   [N,128] @ [128,64]
// 256 threads / 8 warps; 128 rows/block; warp w -> rows [16w,16w+16)
// Xs[128][136] fp16, Wt[64][136] fp16 = Wf^T ([n][k]); dynamic smem ~52KB
// pad 136 halfs = 68 words/row == 4 mod 32: fragment loads conflict-free
// ------------------------------------------------------------------
__global__ void former1_mma(const float* __restrict__ x,
                            const float* __restrict__ Wf,
                            const float* __restrict__ bf) {
    extern __shared__ __half dynh[];
    __half (*Xs)[IN_F + 8] = (__half(*)[IN_F + 8])dynh;                  // 128 rows
    __half (*Wt)[IN_F + 8] = (__half(*)[IN_F + 8])(dynh + 128 * (IN_F + 8));
    float* bs = (float*)(dynh + (128 + 64) * (IN_F + 8));

    int tid  = threadIdx.x;
    int warp = tid >> 5, lane = tid & 31;
    int row0b = blockIdx.x * 128;

    // stage Wf[k][n] -> Wt[n][k] fp16
    for (int idx = tid; idx < IN_F * HID; idx += 256) {
        int k = idx >> 6, n = idx & 63;
        Wt[n][k] = __float2half(Wf[idx]);
    }
    if (tid < HID) bs[tid] = bf[tid];
    // stage x rows -> Xs fp16 (coalesced float4 loads)
    for (int idx = tid; idx < 128 * (IN_F / 4); idx += 256) {
        int row = idx >> 5, kg = idx & 31;
        int gr = min(row0b + row, NN - 1);
        float4 v = *(const float4*)&x[gr * IN_F + kg * 4];
        __half2* d = (__half2*)&Xs[row][kg * 4];
        d[0] = __floats2half2_rn(v.x, v.y);
        d[1] = __floats2half2_rn(v.z, v.w);
    }
    __syncthreads();

    int gr = lane >> 2, tg = lane & 3;
    int m0 = warp * 16;

    float acc[8][4];
#pragma unroll
    for (int nf = 0; nf < 8; nf++)
#pragma unroll
        for (int j = 0; j < 4; j++) acc[nf][j] = 0.f;

#pragma unroll
    for (int ks = 0; ks < 8; ks++) {
        int ac = ks * 16 + tg * 2;
        unsigned a0 = *(const unsigned*)&Xs[m0 + gr][ac];
        unsigned a1 = *(const unsigned*)&Xs[m0 + gr + 8][ac];
        unsigned a2 = *(const unsigned*)&Xs[m0 + gr][ac + 8];
        unsigned a3 = *(const unsigned*)&Xs[m0 + gr + 8][ac + 8];
#pragma unroll
        for (int nf = 0; nf < 8; nf++) {
            unsigned b0 = *(const unsigned*)&Wt[nf * 8 + gr][ac];
            unsigned b1 = *(const unsigned*)&Wt[nf * 8 + gr][ac + 8];
            mma16816(acc[nf], a0, a1, a2, a3, b0, b1);
        }
    }

    int r0 = row0b + m0 + gr;
#pragma unroll
    for (int nf = 0; nf < 8; nf++) {
        int col = nf * 8 + tg * 2;
        if (r0 < NN) {
            float2 v = make_float2(acc[nf][0] + bs[col], acc[nf][1] + bs[col + 1]);
            *(float2*)&g_h[r0 * HID + col] = v;
        }
        if (r0 + 8 < NN) {
            float2 v = make_float2(acc[nf][2] + bs[col], acc[nf][3] + bs[col + 1]);
            *(float2*)&g_h[(r0 + 8) * HID + col] = v;
        }
    }
}
#define F1_SMEM (((128 + 64) * (IN_F + 8)) * 2 + HID * 4)

// ------------------------------------------------------------------
// layer GEMM (mma): D[128rows,128cols] = h @ [convW | linW]
//   cols 0-63  -> g_hws = fp16(dinv*D)    cols 64-127 -> g_r = D + bias
// 256 threads / 8 warps; 128 rows/block
// Hs[128][72] fp16, Wt2[128][72] fp16 ([n][k]); static ~37KB
// ------------------------------------------------------------------
__global__ void layer_mma(const float* __restrict__ convW,
                          const float* __restrict__ convB,
                          const float* __restrict__ linW,
                          const float* __restrict__ linB) {
    __shared__ __half Hs[128][HID + 8];
    __shared__ __half Wt2[128][HID + 8];

    int tid  = threadIdx.x;
    int warp = tid >> 5, lane = tid & 31;
    int row0b = blockIdx.x * 128;

    // stage combined weights: Wt2[j][k] = (j<64 ? convW : linW)[k][j%64]
    for (int idx = tid; idx < HID * 128; idx += 256) {
        int k = idx >> 7, j = idx & 127;
        float w = (j < 64) ? convW[k * 64 + j] : linW[k * 64 + j - 64];
        Wt2[j][k] = __float2half(w);
    }
    // stage h rows fp32 -> fp16
    for (int idx = tid; idx < 128 * (HID / 4); idx += 256) {
        int row = idx >> 4, kg = idx & 15;
        int gr = min(row0b + row, NN - 1);
        float4 v = *(const float4*)&g_h[gr * HID + kg * 4];
        __half2* d = (__half2*)&Hs[row][kg * 4];
        d[0] = __floats2half2_rn(v.x, v.y);
        d[1] = __floats2half2_rn(v.z, v.w);
    }
    __syncthreads();

    int gr = lane >> 2, tg = lane & 3;
    int m0 = warp * 16;

    float acc[16][4];
#pragma unroll
    for (int nf = 0; nf < 16; nf++)
#pragma unroll
        for (int j = 0; j < 4; j++) acc[nf][j] = 0.f;

#pragma unroll
    for (int ks = 0; ks < 4; ks++) {
        int ac = ks * 16 + tg * 2;
        unsigned a0 = *(const unsigned*)&Hs[m0 + gr][ac];
        unsigned a1 = *(const unsigned*)&Hs[m0 + gr + 8][ac];
        unsigned a2 = *(const unsigned*)&Hs[m0 + gr][ac + 8];
        unsigned a3 = *(const unsigned*)&Hs[m0 + gr + 8][ac + 8];
#pragma unroll
        for (int nf = 0; nf < 16; nf++) {
            unsigned b0 = *(const unsigned*)&Wt2[nf * 8 + gr][ac];
            unsigned b1 = *(const unsigned*)&Wt2[nf * 8 + gr][ac + 8];
            mma16816(acc[nf], a0, a1, a2, a3, b0, b1);
        }
    }

    int r0 = row0b + m0 + gr;
    int r1 = r0 + 8;
    bool ok0 = (r0 < NN), ok1 = (r1 < NN);
    float dv0 = ok0 ? g_dinv[r0] : 0.f;
    float dv1 = ok1 ? g_dinv[r1] : 0.f;
#pragma unroll
    for (int nf = 0; nf < 16; nf++) {
        int colc = nf * 8 + tg * 2;          // combined col
        if (colc < 64) {                     // conv branch -> fp16 hws
            if (ok0) {
                __half2 h = __floats2half2_rn(acc[nf][0] * dv0, acc[nf][1] * dv0);
                *(__half2*)&g_hws[r0 * HID + colc] = h;
            }
            if (ok1) {
                __half2 h = __floats2half2_rn(acc[nf][2] * dv1, acc[nf][3] * dv1);
                *(__half2*)&g_hws[r1 * HID + colc] = h;
            }
        } else {                             // residual branch -> fp32 r
            int col = colc - 64;
            float b0 = __ldg(&convB[col])     + __ldg(&linB[col]);
            float b1 = __ldg(&convB[col + 1]) + __ldg(&linB[col + 1]);
            if (ok0) {
                float2 v = make_float2(acc[nf][0] + b0, acc[nf][1] + b1);
                *(float2*)&g_r[r0 * HID + col] = v;
            }
            if (ok1) {
                float2 v = make_float2(acc[nf][2] + b0, acc[nf][3] + b1);
                *(float2*)&g_r[r1 * HID + col] = v;
            }
        }
    }
}

// ------------------------------------------------------------------
// aggregation: h = relu(BN( dn*(sum_e hws[src] + hws[node]) + r[node] ))
// warp per node, half2 gather per lane, 8-deep independent gather chains
// ------------------------------------------------------------------
__global__ void agg_k(const float* __restrict__ gamma,
                      const float* __restrict__ beta,
                      const float* __restrict__ mean,
                      const float* __restrict__ var) {
    int warp = threadIdx.x >> 5;
    int lane = threadIdx.x & 31;
    int node = blockIdx.x * 8 + warp;
    if (node >= NN) return;

    int c = lane * 2;
    float dn  = g_dinv[node];
    int   beg = g_start[node];
    int   end = beg + g_cnt[node];

    const __half2* hws = (const __half2*)g_hws;
    float2 a = __half22float2(hws[node * 32 + lane]);   // self term

    int i = beg;
    for (; i + 8 <= end; i += 8) {
        int s[8];
#pragma unroll
        for (int j = 0; j < 8; j++) s[j] = __ldg(&g_srcbuf[i + j]);
        float2 v[8];
#pragma unroll
        for (int j = 0; j < 8; j++)
            v[j] = __half22float2(__ldg(&hws[s[j] * 32 + lane]));
        float2 t0, t1, t2, t3;
        t0.x = v[0].x + v[1].x; t0.y = v[0].y + v[1].y;
        t1.x = v[2].x + v[3].x; t1.y = v[2].y + v[3].y;
        t2.x = v[4].x + v[5].x; t2.y = v[4].y + v[5].y;
        t3.x = v[6].x + v[7].x; t3.y = v[6].y + v[7].y;
        a.x += (t0.x + t1.x) + (t2.x + t3.x);
        a.y += (t0.y + t1.y) + (t2.y + t3.y);
    }
    for (; i < end; i++) {
        int s = __ldg(&g_srcbuf[i]);
        float2 v = __half22float2(__ldg(&hws[s * 32 + lane]));
        a.x += v.x;
        a.y += v.y;
    }

    float2 rr = ((const float2*)g_r)[node * 32 + lane];
    a.x = a.x * dn + rr.x;
    a.y = a.y * dn + rr.y;

    float s0 = gamma[c]     * rsqrtf(var[c]     + 1e-5f);
    float s1 = gamma[c + 1] * rsqrtf(var[c + 1] + 1e-5f);
    float2 o;
    o.x = fmaxf((a.x - mean[c])     * s0 + beta[c],     0.f);
    o.y = fmaxf((a.y - mean[c + 1]) * s1 + beta[c + 1], 0.f);
    ((float2*)g_h)[node * 32 + lane] = o;
}

// ------------------------------------------------------------------
// pred head: out = h @ predW + predB   [N,64] @ [64,40]
// ------------------------------------------------------------------
__global__ void pred_k(const float* __restrict__ Wp,
                       const float* __restrict__ bp,
                       float* __restrict__ out) {
    __shared__ float Ws[HID * OUT_F];
    __shared__ float bs[OUT_F];
    int tid = threadIdx.x;
    for (int idx = tid; idx < HID * OUT_F; idx += 256) Ws[idx] = Wp[idx];
    if (tid < OUT_F) bs[tid] = bp[tid];
    __syncthreads();
    if (tid >= 240) return;

    int col  = tid % OUT_F;
    int grp  = tid / OUT_F;
    int row0 = blockIdx.x * 24 + grp * 4;
    int r[4];
#pragma unroll
    for (int rr = 0; rr < 4; rr++) r[rr] = min(row0 + rr, NN - 1);

    float acc[4] = {};
    for (int k = 0; k < HID; k += 4) {
        float4 hv[4];
#pragma unroll
        for (int rr = 0; rr < 4; rr++)
            hv[rr] = *(const float4*)&g_h[r[rr] * HID + k];
#pragma unroll
        for (int kk = 0; kk < 4; kk++) {
            float w = Ws[(k + kk) * OUT_F + col];
#pragma unroll
            for (int rr = 0; rr < 4; rr++) {
                float xs = (kk == 0) ? hv[rr].x : (kk == 1) ? hv[rr].y
                         : (kk == 2) ? hv[rr].z : hv[rr].w;
                acc[rr] += xs * w;
            }
        }
    }
#pragma unroll
    for (int rr = 0; rr < 4; rr++) {
        int row = row0 + rr;
        if (row < NN) out[row * OUT_F + col] = acc[rr] + bs[col];
    }
}

// ------------------------------------------------------------------
extern "C" void kernel_launch(void* const* d_in, const int* in_sizes, int n_in,
                              void* d_out, int out_size) {
    const float* x     = (const float*)d_in[0];
    const int*   ei    = (const int*)  d_in[1];
    const float* Wf    = (const float*)d_in[2];
    const float* bf    = (const float*)d_in[3];
    const float* convW = (const float*)d_in[4];
    const float* convB = (const float*)d_in[5];
    const float* linW  = (const float*)d_in[6];
    const float* linB  = (const float*)d_in[7];
    const float* gamma = (const float*)d_in[8];
    const float* beta  = (const float*)d_in[9];
    const float* rmean = (const float*)d_in[10];
    const float* rvar  = (const float*)d_in[11];
    const float* predW = (const float*)d_in[12];
    const float* predB = (const float*)d_in[13];
    float* out = (float*)d_out;

    cudaFuncSetAttribute(former1_mma,
                         cudaFuncAttributeMaxDynamicSharedMemorySize, F1_SMEM);

    void* cnt_ptr = nullptr;
    cudaGetSymbolAddress(&cnt_ptr, g_cnt);
    cudaMemsetAsync(cnt_ptr, 0, NN * sizeof(int), 0);

    count_deg_k <<<(EE / 8 + 255) / 256, 256>>>(ei);
    start_k     <<<(NN + 255) / 256, 256>>>();
    fill_k      <<<(EE / 8 + 255) / 256, 256>>>(ei);

    former1_mma<<<(NN + 127) / 128, 256, F1_SMEM>>>(x, Wf, bf);

    for (int l = 0; l < NLAYER; l++) {
        layer_mma<<<(NN + 127) / 128, 256>>>(
            convW + l * HID * HID, convB + l * HID,
            linW  + l * HID * HID, linB  + l * HID);
        agg_k<<<(NN + 7) / 8, 256>>>(
            gamma + l * HID, beta + l * HID,
            rmean + l * HID, rvar + l * HID);
    }

    pred_k<<<(NN + 23) / 24, 256>>>(predW, predB, out);
}

// round 15
// speedup vs baseline: 1.2881x; 1.2881x over previous
#include <cuda_runtime.h>
#include <cuda_fp16.h>

#define NN 50000
#define EE 800000
#define IN_F 128
#define HID 64
#define OUT_F 40
#define NLAYER 3

// ---- scratch (device globals: no allocation allowed) ----
__device__ __align__(16) float  g_h[NN * HID];    // layer activations (fp32)
__device__ __align__(16) __half g_hws[NN * HID];  // dinv-prescaled conv output (fp16 gather payload)
__device__ __align__(16) float  g_r[NN * HID];    // residual path output (fp32)
__device__ float g_dinv[NN];
__device__ int   g_cnt[NN];
__device__ int   g_start[NN];
__device__ int   g_fill[NN];
__device__ int   g_srcbuf[EE];
__device__ int   g_total;

// ---- mma.sync m16n8k16 row.col f32.f16.f16.f32 (base sm_80+ PTX) ----
__device__ __forceinline__ void mma16816(float (&c)[4],
                                         unsigned a0, unsigned a1,
                                         unsigned a2, unsigned a3,
                                         unsigned b0, unsigned b1) {
    asm volatile(
        "mma.sync.aligned.m16n8k16.row.col.f32.f16.f16.f32 "
        "{%0,%1,%2,%3}, {%4,%5,%6,%7}, {%8,%9}, {%0,%1,%2,%3};\n"
        : "+f"(c[0]), "+f"(c[1]), "+f"(c[2]), "+f"(c[3])
        : "r"(a0), "r"(a1), "r"(a2), "r"(a3), "r"(b0), "r"(b1));
}

// ------------------------------------------------------------------
// CSR build (unordered segments: starts assigned by atomic bump)
// 4 edges/thread (R13-proven: thread count IS the MLP here)
// ------------------------------------------------------------------
__global__ void count_deg_k(const int* __restrict__ ei) {
    if (blockIdx.x == 0 && threadIdx.x == 0) g_total = 0;
    int e0 = (blockIdx.x * 256 + threadIdx.x) * 4;
    if (e0 < EE) {
        int4 d4 = *(const int4*)&ei[EE + e0];
        atomicAdd(&g_cnt[d4.x], 1);
        atomicAdd(&g_cnt[d4.y], 1);
        atomicAdd(&g_cnt[d4.z], 1);
        atomicAdd(&g_cnt[d4.w], 1);
    }
}

__global__ void start_k() {
    int i = blockIdx.x * 256 + threadIdx.x;
    if (i < NN) {
        int c = g_cnt[i];
        g_dinv[i] = rsqrtf((float)c + 1.0f);
        int s = atomicAdd(&g_total, c);
        g_start[i] = s;
        g_fill[i]  = s;
    }
}

__global__ void fill_k(const int* __restrict__ ei) {
    int e0 = (blockIdx.x * 256 + threadIdx.x) * 4;
    if (e0 < EE) {
        int4 s4 = *(const int4*)&ei[e0];
        int4 d4 = *(const int4*)&ei[EE + e0];
        int p0 = atomicAdd(&g_fill[d4.x], 1);
        int p1 = atomicAdd(&g_fill[d4.y], 1);
        int p2 = atomicAdd(&g_fill[d4.z], 1);
        int p3 = atomicAdd(&g_fill[d4.w], 1);
        g_srcbuf[p0] = s4.x;
        g_srcbuf[p1] = s4.y;
        g_srcbuf[p2] = s4.z;
        g_srcbuf[p3] = s4.w;
    }
}

// ------------------------------------------------------------------
// former1 (mma): h = x @ Wf + bf   [N,128] @ [128,64]
// 128 threads / 4 warps; 64 rows/block; warp w -> rows [16w,16w+16)
// Xs[64][136] fp16, Wt[64][136] fp16 = Wf^T ([n][k])
// pad 136 halfs = 68 words/row == 4 mod 32: fragment loads conflict-free
// ------------------------------------------------------------------
__global__ void former1_mma(const float* __restrict__ x,
                            const float* __restrict__ Wf,
                            const float* __restrict__ bf) {
    __shared__ __half Xs[64][IN_F + 8];
    __shared__ __half Wt[HID][IN_F + 8];
    __shared__ float  bs[HID];

    int tid  = threadIdx.x;
    int warp = tid >> 5, lane = tid & 31;
    int row0b = blockIdx.x * 64;

    // stage Wf[k][n] -> Wt[n][k] fp16
    for (int idx = tid; idx < IN_F * HID; idx += 128) {
        int k = idx >> 6, n = idx & 63;
        Wt[n][k] = __float2half(Wf[idx]);
    }
    if (tid < HID) bs[tid] = bf[tid];
    // stage x rows -> Xs fp16
    for (int idx = tid; idx < 64 * (IN_F / 4); idx += 128) {
        int row = idx >> 5, kg = idx & 31;
        int gr = min(row0b + row, NN - 1);
        float4 v = *(const float4*)&x[gr * IN_F + kg * 4];
        __half2* d = (__half2*)&Xs[row][kg * 4];
        d[0] = __floats2half2_rn(v.x, v.y);
        d[1] = __floats2half2_rn(v.z, v.w);
    }
    __syncthreads();

    int gr = lane >> 2, tg = lane & 3;
    int m0 = warp * 16;

    float acc[8][4];
#pragma unroll
    for (int nf = 0; nf < 8; nf++)
#pragma unroll
        for (int j = 0; j < 4; j++) acc[nf][j] = 0.f;

#pragma unroll
    for (int ks = 0; ks < 8; ks++) {
        int ac = ks * 16 + tg * 2;
        unsigned a0 = *(const unsigned*)&Xs[m0 + gr][ac];
        unsigned a1 = *(const unsigned*)&Xs[m0 + gr + 8][ac];
        unsigned a2 = *(const unsigned*)&Xs[m0 + gr][ac + 8];
        unsigned a3 = *(const unsigned*)&Xs[m0 + gr + 8][ac + 8];
#pragma unroll
        for (int nf = 0; nf < 8; nf++) {
            unsigned b0 = *(const unsigned*)&Wt[nf * 8 + gr][ac];
            unsigned b1 = *(const unsigned*)&Wt[nf * 8 + gr][ac + 8];
            mma16816(acc[nf], a0, a1, a2, a3, b0, b1);
        }
    }

    int r0 = row0b + m0 + gr;
#pragma unroll
    for (int nf = 0; nf < 8; nf++) {
        int col = nf * 8 + tg * 2;
        if (r0 < NN) {
            float2 v = make_float2(acc[nf][0] + bs[col], acc[nf][1] + bs[col + 1]);
            *(float2*)&g_h[r0 * HID + col] = v;
        }
        if (r0 + 8 < NN) {
            float2 v = make_float2(acc[nf][2] + bs[col], acc[nf][3] + bs[col + 1]);
            *(float2*)&g_h[(r0 + 8) * HID + col] = v;
        }
    }
}

// ------------------------------------------------------------------
// layer GEMM (mma): D[64rows,128cols] = h @ [convW | linW]
//   cols 0-63  -> g_hws = fp16(dinv*D)    cols 64-127 -> g_r = D + bias
// 128 threads / 4 warps; 64 rows/block
// Hs[64][72] fp16, Wt2[128][72] fp16 ([n][k]); pad 72 -> 36 words == 4 mod 32
// ------------------------------------------------------------------
__global__ void layer_mma(const float* __restrict__ convW,
                          const float* __restrict__ convB,
                          const float* __restrict__ linW,
                          const float* __restrict__ linB) {
    __shared__ __half Hs[64][HID + 8];
    __shared__ __half Wt2[128][HID + 8];

    int tid  = threadIdx.x;
    int warp = tid >> 5, lane = tid & 31;
    int row0b = blockIdx.x * 64;

    // stage combined weights: Wt2[j][k] = (j<64 ? convW : linW)[k][j%64]
    for (int idx = tid; idx < HID * 128; idx += 128) {
        int k = idx >> 7, j = idx & 127;
        float w = (j < 64) ? convW[k * 64 + j] : linW[k * 64 + j - 64];
        Wt2[j][k] = __float2half(w);
    }
    // stage h rows fp32 -> fp16
    for (int idx = tid; idx < 64 * (HID / 4); idx += 128) {
        int row = idx >> 4, kg = idx & 15;
        int gr = min(row0b + row, NN - 1);
        float4 v = *(const float4*)&g_h[gr * HID + kg * 4];
        __half2* d = (__half2*)&Hs[row][kg * 4];
        d[0] = __floats2half2_rn(v.x, v.y);
        d[1] = __floats2half2_rn(v.z, v.w);
    }
    __syncthreads();

    int gr = lane >> 2, tg = lane & 3;
    int m0 = warp * 16;

    float acc[16][4];
#pragma unroll
    for (int nf = 0; nf < 16; nf++)
#pragma unroll
        for (int j = 0; j < 4; j++) acc[nf][j] = 0.f;

#pragma unroll
    for (int ks = 0; ks < 4; ks++) {
        int ac = ks * 16 + tg * 2;
        unsigned a0 = *(const unsigned*)&Hs[m0 + gr][ac];
        unsigned a1 = *(const unsigned*)&Hs[m0 + gr + 8][ac];
        unsigned a2 = *(const unsigned*)&Hs[m0 + gr][ac + 8];
        unsigned a3 = *(const unsigned*)&Hs[m0 + gr + 8][ac + 8];
#pragma unroll
        for (int nf = 0; nf < 16; nf++) {
            unsigned b0 = *(const unsigned*)&Wt2[nf * 8 + gr][ac];
            unsigned b1 = *(const unsigned*)&Wt2[nf * 8 + gr][ac + 8];
            mma16816(acc[nf], a0, a1, a2, a3, b0, b1);
        }
    }

    int r0 = row0b + m0 + gr;
    int r1 = r0 + 8;
    bool ok0 = (r0 < NN), ok1 = (r1 < NN);
    float dv0 = ok0 ? g_dinv[r0] : 0.f;
    float dv1 = ok1 ? g_dinv[r1] : 0.f;
#pragma unroll
    for (int nf = 0; nf < 16; nf++) {
        int colc = nf * 8 + tg * 2;          // combined col
        if (colc < 64) {                     // conv branch -> fp16 hws
            if (ok0) {
                __half2 h = __floats2half2_rn(acc[nf][0] * dv0, acc[nf][1] * dv0);
                *(__half2*)&g_hws[r0 * HID + colc] = h;
            }
            if (ok1) {
                __half2 h = __floats2half2_rn(acc[nf][2] * dv1, acc[nf][3] * dv1);
                *(__half2*)&g_hws[r1 * HID + colc] = h;
            }
        } else {                             // residual branch -> fp32 r
            int col = colc - 64;
            float b0 = __ldg(&convB[col])     + __ldg(&linB[col]);
            float b1 = __ldg(&convB[col + 1]) + __ldg(&linB[col + 1]);
            if (ok0) {
                float2 v = make_float2(acc[nf][0] + b0, acc[nf][1] + b1);
                *(float2*)&g_r[r0 * HID + col] = v;
            }
            if (ok1) {
                float2 v = make_float2(acc[nf][2] + b0, acc[nf][3] + b1);
                *(float2*)&g_r[r1 * HID + col] = v;
            }
        }
    }
}

// ------------------------------------------------------------------
// aggregation: h = relu(BN( dn*(sum_e hws[src] + hws[node]) + r[node] ))
// warp per node, half2 gather per lane; software-pipelined: next batch's
// indices prefetched while current batch's row gathers are in flight
// ------------------------------------------------------------------
__global__ void agg_k(const float* __restrict__ gamma,
                      const float* __restrict__ beta,
                      const float* __restrict__ mean,
                      const float* __restrict__ var) {
    int warp = threadIdx.x >> 5;
    int lane = threadIdx.x & 31;
    int node = blockIdx.x * 8 + warp;
    if (node >= NN) return;

    int c = lane * 2;
    float dn  = g_dinv[node];
    int   beg = g_start[node];
    int   end = beg + g_cnt[node];

    const __half2* hws = (const __half2*)g_hws;
    float2 a = __half22float2(hws[node * 32 + lane]);   // self term

    int i = beg;
    if (i + 8 <= end) {
        int s[8];
#pragma unroll
        for (int j = 0; j < 8; j++) s[j] = __ldg(&g_srcbuf[i + j]);
        i += 8;
        while (i + 8 <= end) {
            int sn[8];
#pragma unroll
            for (int j = 0; j < 8; j++) sn[j] = __ldg(&g_srcbuf[i + j]);
            float2 v[8];
#pragma unroll
            for (int j = 0; j < 8; j++)
                v[j] = __half22float2(__ldg(&hws[s[j] * 32 + lane]));
            a.x += ((v[0].x + v[1].x) + (v[2].x + v[3].x))
                 + ((v[4].x + v[5].x) + (v[6].x + v[7].x));
            a.y += ((v[0].y + v[1].y) + (v[2].y + v[3].y))
                 + ((v[4].y + v[5].y) + (v[6].y + v[7].y));
#pragma unroll
            for (int j = 0; j < 8; j++) s[j] = sn[j];
            i += 8;
        }
        {   // drain last prefetched batch
            float2 v[8];
#pragma unroll
            for (int j = 0; j < 8; j++)
                v[j] = __half22float2(__ldg(&hws[s[j] * 32 + lane]));
            a.x += ((v[0].x + v[1].x) + (v[2].x + v[3].x))
                 + ((v[4].x + v[5].x) + (v[6].x + v[7].x));
            a.y += ((v[0].y + v[1].y) + (v[2].y + v[3].y))
                 + ((v[4].y + v[5].y) + (v[6].y + v[7].y));
        }
    }
    for (; i < end; i++) {
        int s = __ldg(&g_srcbuf[i]);
        float2 v = __half22float2(__ldg(&hws[s * 32 + lane]));
        a.x += v.x;
        a.y += v.y;
    }

    float2 rr = ((const float2*)g_r)[node * 32 + lane];
    a.x = a.x * dn + rr.x;
    a.y = a.y * dn + rr.y;

    float s0 = gamma[c]     * rsqrtf(var[c]     + 1e-5f);
    float s1 = gamma[c + 1] * rsqrtf(var[c + 1] + 1e-5f);
    float2 o;
    o.x = fmaxf((a.x - mean[c])     * s0 + beta[c],     0.f);
    o.y = fmaxf((a.y - mean[c + 1]) * s1 + beta[c + 1], 0.f);
    ((float2*)g_h)[node * 32 + lane] = o;
}

// ------------------------------------------------------------------
// pred head: out = h @ predW + predB   [N,64] @ [64,40]
// ------------------------------------------------------------------
__global__ void pred_k(const float* __restrict__ Wp,
                       const float* __restrict__ bp,
                       float* __restrict__ out) {
    __shared__ float Ws[HID * OUT_F];
    __shared__ float bs[OUT_F];
    int tid = threadIdx.x;
    for (int idx = tid; idx < HID * OUT_F; idx += 256) Ws[idx] = Wp[idx];
    if (tid < OUT_F) bs[tid] = bp[tid];
    __syncthreads();
    if (tid >= 240) return;

    int col  = tid % OUT_F;
    int grp  = tid / OUT_F;
    int row0 = blockIdx.x * 24 + grp * 4;
    int r[4];
#pragma unroll
    for (int rr = 0; rr < 4; rr++) r[rr] = min(row0 + rr, NN - 1);

    float acc[4] = {};
    for (int k = 0; k < HID; k += 4) {
        float4 hv[4];
#pragma unroll
        for (int rr = 0; rr < 4; rr++)
            hv[rr] = *(const float4*)&g_h[r[rr] * HID + k];
#pragma unroll
        for (int kk = 0; kk < 4; kk++) {
            float w = Ws[(k + kk) * OUT_F + col];
#pragma unroll
            for (int rr = 0; rr < 4; rr++) {
                float xs = (kk == 0) ? hv[rr].x : (kk == 1) ? hv[rr].y
                         : (kk == 2) ? hv[rr].z : hv[rr].w;
                acc[rr] += xs * w;
            }
        }
    }
#pragma unroll
    for (int rr = 0; rr < 4; rr++) {
        int row = row0 + rr;
        if (row < NN) out[row * OUT_F + col] = acc[rr] + bs[col];
    }
}

// ------------------------------------------------------------------
extern "C" void kernel_launch(void* const* d_in, const int* in_sizes, int n_in,
                              void* d_out, int out_size) {
    const float* x     = (const float*)d_in[0];
    const int*   ei    = (const int*)  d_in[1];
    const float* Wf    = (const float*)d_in[2];
    const float* bf    = (const float*)d_in[3];
    const float* convW = (const float*)d_in[4];
    const float* convB = (const float*)d_in[5];
    const float* linW  = (const float*)d_in[6];
    const float* linB  = (const float*)d_in[7];
    const float* gamma = (const float*)d_in[8];
    const float* beta  = (const float*)d_in[9];
    const float* rmean = (const float*)d_in[10];
    const float* rvar  = (const float*)d_in[11];
    const float* predW = (const float*)d_in[12];
    const float* predB = (const float*)d_in[13];
    float* out = (float*)d_out;

    void* cnt_ptr = nullptr;
    cudaGetSymbolAddress(&cnt_ptr, g_cnt);
    cudaMemsetAsync(cnt_ptr, 0, NN * sizeof(int), 0);

    count_deg_k <<<(EE / 4 + 255) / 256, 256>>>(ei);
    start_k     <<<(NN + 255) / 256, 256>>>();
    fill_k      <<<(EE / 4 + 255) / 256, 256>>>(ei);

    former1_mma<<<(NN + 63) / 64, 128>>>(x, Wf, bf);

    for (int l = 0; l < NLAYER; l++) {
        layer_mma<<<(NN + 63) / 64, 128>>>(
            convW + l * HID * HID, convB + l * HID,
            linW  + l * HID * HID, linB  + l * HID);
        agg_k<<<(NN + 7) / 8, 256>>>(
            gamma + l * HID, beta + l * HID,
            rmean + l * HID, rvar + l * HID);
    }

    pred_k<<<(NN + 23) / 24, 256>>>(predW, predB, out);
}

// round 16
// speedup vs baseline: 1.4529x; 1.1280x over previous
#include <cuda_runtime.h>
#include <cuda_fp16.h>

#define NN 50000
#define EE 800000
#define IN_F 128
#define HID 64
#define OUT_F 40
#define NLAYER 3

// ---- scratch (device globals: no allocation allowed) ----
__device__ __align__(16) float  g_h[NN * HID];    // layer activations (fp32)
__device__ __align__(16) __half g_hws[NN * HID];  // dinv-prescaled conv output (fp16 gather payload)
__device__ __align__(16) float  g_r[NN * HID];    // residual path output (fp32)
__device__ float g_dinv[NN];
__device__ int   g_cnt[NN];
__device__ int   g_start[NN];
__device__ int   g_fill[NN];
__device__ int   g_srcbuf[EE];
__device__ int   g_total;
// pre-transposed fp16 weight images (padded to the smem tile layout)
__device__ __align__(16) __half g_WtF[HID][IN_F + 8];            // Wf^T
__device__ __align__(16) __half g_Wt2[NLAYER][128][HID + 8];     // [convW|linW]^T per layer

// ---- mma.sync m16n8k16 row.col f32.f16.f16.f32 (base sm_80+ PTX) ----
__device__ __forceinline__ void mma16816(float (&c)[4],
                                         unsigned a0, unsigned a1,
                                         unsigned a2, unsigned a3,
                                         unsigned b0, unsigned b1) {
    asm volatile(
        "mma.sync.aligned.m16n8k16.row.col.f32.f16.f16.f32 "
        "{%0,%1,%2,%3}, {%4,%5,%6,%7}, {%8,%9}, {%0,%1,%2,%3};\n"
        : "+f"(c[0]), "+f"(c[1]), "+f"(c[2]), "+f"(c[3])
        : "r"(a0), "r"(a1), "r"(a2), "r"(a3), "r"(b0), "r"(b1));
}

// ------------------------------------------------------------------
// one-shot weight prep: fp32 -> fp16 transposed images
// ------------------------------------------------------------------
__global__ void prep_w_k(const float* __restrict__ Wf,
                         const float* __restrict__ convW,
                         const float* __restrict__ linW) {
    int idx = blockIdx.x * 256 + threadIdx.x;
    if (idx < IN_F * HID) {                      // former1: Wf[k][n] -> [n][k]
        int k = idx >> 6, n = idx & 63;
        g_WtF[n][k] = __float2half(Wf[idx]);
    } else if (idx < IN_F * HID + NLAYER * HID * 128) {
        int t = idx - IN_F * HID;
        int l = t >> 13;
        int r = t & 8191;
        int k = r >> 7, j = r & 127;
        float w = (j < 64) ? convW[l * 4096 + k * 64 + j]
                           : linW[l * 4096 + k * 64 + (j - 64)];
        g_Wt2[l][j][k] = __float2half(w);
    }
}

// ------------------------------------------------------------------
// CSR build (unordered segments: starts assigned by atomic bump)
// ------------------------------------------------------------------
__global__ void count_deg_k(const int* __restrict__ ei) {
    if (blockIdx.x == 0 && threadIdx.x == 0) g_total = 0;
    int e0 = (blockIdx.x * 256 + threadIdx.x) * 4;
    if (e0 < EE) {
        int4 d4 = *(const int4*)&ei[EE + e0];
        atomicAdd(&g_cnt[d4.x], 1);
        atomicAdd(&g_cnt[d4.y], 1);
        atomicAdd(&g_cnt[d4.z], 1);
        atomicAdd(&g_cnt[d4.w], 1);
    }
}

__global__ void start_k() {
    int i = blockIdx.x * 256 + threadIdx.x;
    if (i < NN) {
        int c = g_cnt[i];
        g_dinv[i] = rsqrtf((float)c + 1.0f);
        int s = atomicAdd(&g_total, c);
        g_start[i] = s;
        g_fill[i]  = s;
    }
}

__global__ void fill_k(const int* __restrict__ ei) {
    int e0 = (blockIdx.x * 256 + threadIdx.x) * 4;
    if (e0 < EE) {
        int4 s4 = *(const int4*)&ei[e0];
        int4 d4 = *(const int4*)&ei[EE + e0];
        int p0 = atomicAdd(&g_fill[d4.x], 1);
        int p1 = atomicAdd(&g_fill[d4.y], 1);
        int p2 = atomicAdd(&g_fill[d4.z], 1);
        int p3 = atomicAdd(&g_fill[d4.w], 1);
        g_srcbuf[p0] = s4.x;
        g_srcbuf[p1] = s4.y;
        g_srcbuf[p2] = s4.z;
        g_srcbuf[p3] = s4.w;
    }
}

// ------------------------------------------------------------------
// former1 (mma): h = x @ Wf + bf   [N,128] @ [128,64]
// 128 threads / 4 warps; 64 rows/block
// Wt tile copied from pre-transposed g_WtF as straight float4 memcpy
// ------------------------------------------------------------------
__global__ void former1_mma(const float* __restrict__ x,
                            const float* __restrict__ bf) {
    __shared__ __half Xs[64][IN_F + 8];
    __shared__ __half Wt[HID][IN_F + 8];
    __shared__ float  bs[HID];

    int tid  = threadIdx.x;
    int warp = tid >> 5, lane = tid & 31;
    int row0b = blockIdx.x * 64;

    // weight tile: vectorized copy (64*136 halfs = 1088 float4)
    {
        const float4* src = (const float4*)g_WtF;
        float4* dst = (float4*)Wt;
        for (int i = tid; i < (HID * (IN_F + 8)) / 8; i += 128) dst[i] = src[i];
    }
    if (tid < HID) bs[tid] = bf[tid];
    // stage x rows -> Xs fp16
    for (int idx = tid; idx < 64 * (IN_F / 4); idx += 128) {
        int row = idx >> 5, kg = idx & 31;
        int gr = min(row0b + row, NN - 1);
        float4 v = *(const float4*)&x[gr * IN_F + kg * 4];
        __half2* d = (__half2*)&Xs[row][kg * 4];
        d[0] = __floats2half2_rn(v.x, v.y);
        d[1] = __floats2half2_rn(v.z, v.w);
    }
    __syncthreads();

    int gr = lane >> 2, tg = lane & 3;
    int m0 = warp * 16;

    float acc[8][4];
#pragma unroll
    for (int nf = 0; nf < 8; nf++)
#pragma unroll
        for (int j = 0; j < 4; j++) acc[nf][j] = 0.f;

#pragma unroll
    for (int ks = 0; ks < 8; ks++) {
        int ac = ks * 16 + tg * 2;
        unsigned a0 = *(const unsigned*)&Xs[m0 + gr][ac];
        unsigned a1 = *(const unsigned*)&Xs[m0 + gr + 8][ac];
        unsigned a2 = *(const unsigned*)&Xs[m0 + gr][ac + 8];
        unsigned a3 = *(const unsigned*)&Xs[m0 + gr + 8][ac + 8];
#pragma unroll
        for (int nf = 0; nf < 8; nf++) {
            unsigned b0 = *(const unsigned*)&Wt[nf * 8 + gr][ac];
            unsigned b1 = *(const unsigned*)&Wt[nf * 8 + gr][ac + 8];
            mma16816(acc[nf], a0, a1, a2, a3, b0, b1);
        }
    }

    int r0 = row0b + m0 + gr;
#pragma unroll
    for (int nf = 0; nf < 8; nf++) {
        int col = nf * 8 + tg * 2;
        if (r0 < NN) {
            float2 v = make_float2(acc[nf][0] + bs[col], acc[nf][1] + bs[col + 1]);
            *(float2*)&g_h[r0 * HID + col] = v;
        }
        if (r0 + 8 < NN) {
            float2 v = make_float2(acc[nf][2] + bs[col], acc[nf][3] + bs[col + 1]);
            *(float2*)&g_h[(r0 + 8) * HID + col] = v;
        }
    }
}

// ------------------------------------------------------------------
// layer GEMM (mma): D[64rows,128cols] = h @ [convW | linW]
//   cols 0-63  -> g_hws = fp16(dinv*D)    cols 64-127 -> g_r = D + bias
// Wt2 tile copied from pre-transposed g_Wt2[layer] as float4 memcpy
// ------------------------------------------------------------------
__global__ void layer_mma(const float* __restrict__ convB,
                          const float* __restrict__ linB,
                          int layer) {
    __shared__ __half Hs[64][HID + 8];
    __shared__ __half Wt2[128][HID + 8];

    int tid  = threadIdx.x;
    int warp = tid >> 5, lane = tid & 31;
    int row0b = blockIdx.x * 64;

    // weight tile: vectorized copy (128*72 halfs = 1152 float4)
    {
        const float4* src = (const float4*)g_Wt2[layer];
        float4* dst = (float4*)Wt2;
        for (int i = tid; i < (128 * (HID + 8)) / 8; i += 128) dst[i] = src[i];
    }
    // stage h rows fp32 -> fp16
    for (int idx = tid; idx < 64 * (HID / 4); idx += 128) {
        int row = idx >> 4, kg = idx & 15;
        int gr = min(row0b + row, NN - 1);
        float4 v = *(const float4*)&g_h[gr * HID + kg * 4];
        __half2* d = (__half2*)&Hs[row][kg * 4];
        d[0] = __floats2half2_rn(v.x, v.y);
        d[1] = __floats2half2_rn(v.z, v.w);
    }
    __syncthreads();

    int gr = lane >> 2, tg = lane & 3;
    int m0 = warp * 16;

    float acc[16][4];
#pragma unroll
    for (int nf = 0; nf < 16; nf++)
#pragma unroll
        for (int j = 0; j < 4; j++) acc[nf][j] = 0.f;

#pragma unroll
    for (int ks = 0; ks < 4; ks++) {
        int ac = ks * 16 + tg * 2;
        unsigned a0 = *(const unsigned*)&Hs[m0 + gr][ac];
        unsigned a1 = *(const unsigned*)&Hs[m0 + gr + 8][ac];
        unsigned a2 = *(const unsigned*)&Hs[m0 + gr][ac + 8];
        unsigned a3 = *(const unsigned*)&Hs[m0 + gr + 8][ac + 8];
#pragma unroll
        for (int nf = 0; nf < 16; nf++) {
            unsigned b0 = *(const unsigned*)&Wt2[nf * 8 + gr][ac];
            unsigned b1 = *(const unsigned*)&Wt2[nf * 8 + gr][ac + 8];
            mma16816(acc[nf], a0, a1, a2, a3, b0, b1);
        }
    }

    int r0 = row0b + m0 + gr;
    int r1 = r0 + 8;
    bool ok0 = (r0 < NN), ok1 = (r1 < NN);
    float dv0 = ok0 ? g_dinv[r0] : 0.f;
    float dv1 = ok1 ? g_dinv[r1] : 0.f;
#pragma unroll
    for (int nf = 0; nf < 16; nf++) {
        int colc = nf * 8 + tg * 2;          // combined col
        if (colc < 64) {                     // conv branch -> fp16 hws
            if (ok0) {
                __half2 h = __floats2half2_rn(acc[nf][0] * dv0, acc[nf][1] * dv0);
                *(__half2*)&g_hws[r0 * HID + colc] = h;
            }
            if (ok1) {
                __half2 h = __floats2half2_rn(acc[nf][2] * dv1, acc[nf][3] * dv1);
                *(__half2*)&g_hws[r1 * HID + colc] = h;
            }
        } else {                             // residual branch -> fp32 r
            int col = colc - 64;
            float b0 = __ldg(&convB[col])     + __ldg(&linB[col]);
            float b1 = __ldg(&convB[col + 1]) + __ldg(&linB[col + 1]);
            if (ok0) {
                float2 v = make_float2(acc[nf][0] + b0, acc[nf][1] + b1);
                *(float2*)&g_r[r0 * HID + col] = v;
            }
            if (ok1) {
                float2 v = make_float2(acc[nf][2] + b0, acc[nf][3] + b1);
                *(float2*)&g_r[r1 * HID + col] = v;
            }
        }
    }
}

// ------------------------------------------------------------------
// aggregation: h = relu(BN( dn*(sum_e hws[src] + hws[node]) + r[node] ))
// warp per node, half2 gather per lane, 8-deep independent gather chains
// ------------------------------------------------------------------
__global__ void agg_k(const float* __restrict__ gamma,
                      const float* __restrict__ beta,
                      const float* __restrict__ mean,
                      const float* __restrict__ var) {
    int warp = threadIdx.x >> 5;
    int lane = threadIdx.x & 31;
    int node = blockIdx.x * 8 + warp;
    if (node >= NN) return;

    int c = lane * 2;
    float dn  = g_dinv[node];
    int   beg = g_start[node];
    int   end = beg + g_cnt[node];

    const __half2* hws = (const __half2*)g_hws;
    float2 a = __half22float2(hws[node * 32 + lane]);   // self term

    int i = beg;
    for (; i + 8 <= end; i += 8) {
        int s[8];
#pragma unroll
        for (int j = 0; j < 8; j++) s[j] = __ldg(&g_srcbuf[i + j]);
        float2 v[8];
#pragma unroll
        for (int j = 0; j < 8; j++)
            v[j] = __half22float2(__ldg(&hws[s[j] * 32 + lane]));
        float2 t0, t1, t2, t3;
        t0.x = v[0].x + v[1].x; t0.y = v[0].y + v[1].y;
        t1.x = v[2].x + v[3].x; t1.y = v[2].y + v[3].y;
        t2.x = v[4].x + v[5].x; t2.y = v[4].y + v[5].y;
        t3.x = v[6].x + v[7].x; t3.y = v[6].y + v[7].y;
        a.x += (t0.x + t1.x) + (t2.x + t3.x);
        a.y += (t0.y + t1.y) + (t2.y + t3.y);
    }
    for (; i < end; i++) {
        int s = __ldg(&g_srcbuf[i]);
        float2 v = __half22float2(__ldg(&hws[s * 32 + lane]));
        a.x += v.x;
        a.y += v.y;
    }

    float2 rr = ((const float2*)g_r)[node * 32 + lane];
    a.x = a.x * dn + rr.x;
    a.y = a.y * dn + rr.y;

    float s0 = gamma[c]     * rsqrtf(var[c]     + 1e-5f);
    float s1 = gamma[c + 1] * rsqrtf(var[c + 1] + 1e-5f);
    float2 o;
    o.x = fmaxf((a.x - mean[c])     * s0 + beta[c],     0.f);
    o.y = fmaxf((a.y - mean[c + 1]) * s1 + beta[c + 1], 0.f);
    ((float2*)g_h)[node * 32 + lane] = o;
}

// ------------------------------------------------------------------
// pred head: out = h @ predW + predB   [N,64] @ [64,40]
// ------------------------------------------------------------------
__global__ void pred_k(const float* __restrict__ Wp,
                       const float* __restrict__ bp,
                       float* __restrict__ out) {
    __shared__ float Ws[HID * OUT_F];
    __shared__ float bs[OUT_F];
    int tid = threadIdx.x;
    for (int idx = tid; idx < HID * OUT_F; idx += 256) Ws[idx] = Wp[idx];
    if (tid < OUT_F) bs[tid] = bp[tid];
    __syncthreads();
    if (tid >= 240) return;

    int col  = tid % OUT_F;
    int grp  = tid / OUT_F;
    int row0 = blockIdx.x * 24 + grp * 4;
    int r[4];
#pragma unroll
    for (int rr = 0; rr < 4; rr++) r[rr] = min(row0 + rr, NN - 1);

    float acc[4] = {};
    for (int k = 0; k < HID; k += 4) {
        float4 hv[4];
#pragma unroll
        for (int rr = 0; rr < 4; rr++)
            hv[rr] = *(const float4*)&g_h[r[rr] * HID + k];
#pragma unroll
        for (int kk = 0; kk < 4; kk++) {
            float w = Ws[(k + kk) * OUT_F + col];
#pragma unroll
            for (int rr = 0; rr < 4; rr++) {
                float xs = (kk == 0) ? hv[rr].x : (kk == 1) ? hv[rr].y
                         : (kk == 2) ? hv[rr].z : hv[rr].w;
                acc[rr] += xs * w;
            }
        }
    }
#pragma unroll
    for (int rr = 0; rr < 4; rr++) {
        int row = row0 + rr;
        if (row < NN) out[row * OUT_F + col] = acc[rr] + bs[col];
    }
}

// ------------------------------------------------------------------
extern "C" void kernel_launch(void* const* d_in, const int* in_sizes, int n_in,
                              void* d_out, int out_size) {
    const float* x     = (const float*)d_in[0];
    const int*   ei    = (const int*)  d_in[1];
    const float* Wf    = (const float*)d_in[2];
    const float* bf    = (const float*)d_in[3];
    const float* convW = (const float*)d_in[4];
    const float* convB = (const float*)d_in[5];
    const float* linW  = (const float*)d_in[6];
    const float* linB  = (const float*)d_in[7];
    const float* gamma = (const float*)d_in[8];
    const float* beta  = (const float*)d_in[9];
    const float* rmean = (const float*)d_in[10];
    const float* rvar  = (const float*)d_in[11];
    const float* predW = (const float*)d_in[12];
    const float* predB = (const float*)d_in[13];
    float* out = (float*)d_out;

    void* cnt_ptr = nullptr;
    cudaGetSymbolAddress(&cnt_ptr, g_cnt);
    cudaMemsetAsync(cnt_ptr, 0, NN * sizeof(int), 0);

    prep_w_k <<<(IN_F * HID + NLAYER * HID * 128 + 255) / 256, 256>>>(Wf, convW, linW);

    count_deg_k <<<(EE / 4 + 255) / 256, 256>>>(ei);
    start_k     <<<(NN + 255) / 256, 256>>>();
    fill_k      <<<(EE / 4 + 255) / 256, 256>>>(ei);

    former1_mma<<<(NN + 63) / 64, 128>>>(x, bf);

    for (int l = 0; l < NLAYER; l++) {
        layer_mma<<<(NN + 63) / 64, 128>>>(convB + l * HID, linB + l * HID, l);
        agg_k<<<(NN + 7) / 8, 256>>>(
            gamma + l * HID, beta + l * HID,
            rmean + l * HID, rvar + l * HID);
    }

    pred_k<<<(NN + 23) / 24, 256>>>(predW, predB, out);
}

// round 17
// speedup vs baseline: 1.4906x; 1.0259x over previous
#include <cuda_runtime.h>
#include <cuda_fp16.h>

#define NN 50000
#define EE 800000
#define IN_F 128
#define HID 64
#define OUT_F 40
#define NLAYER 3

// ---- scratch (device globals: no allocation allowed) ----
__device__ __align__(16) float  g_h[NN * HID];    // layer activations (fp32)
__device__ __align__(16) __half g_hws[NN * HID];  // dinv-prescaled conv output (fp16 gather payload)
__device__ __align__(16) float  g_r[NN * HID];    // residual path output (fp32)
__device__ float g_dinv[NN];
__device__ int   g_cnt[NN];
__device__ int   g_start[NN];
__device__ int   g_fill[NN];
__device__ int   g_srcbuf[EE];
__device__ int   g_total;
// pre-transposed fp16 weight images (padded to the smem tile layout)
__device__ __align__(16) __half g_WtF[HID][IN_F + 8];            // Wf^T
__device__ __align__(16) __half g_Wt2[NLAYER][128][HID + 8];     // [convW|linW]^T per layer

// ---- mma.sync m16n8k16 row.col f32.f16.f16.f32 (base sm_80+ PTX) ----
__device__ __forceinline__ void mma16816(float (&c)[4],
                                         unsigned a0, unsigned a1,
                                         unsigned a2, unsigned a3,
                                         unsigned b0, unsigned b1) {
    asm volatile(
        "mma.sync.aligned.m16n8k16.row.col.f32.f16.f16.f32 "
        "{%0,%1,%2,%3}, {%4,%5,%6,%7}, {%8,%9}, {%0,%1,%2,%3};\n"
        : "+f"(c[0]), "+f"(c[1]), "+f"(c[2]), "+f"(c[3])
        : "r"(a0), "r"(a1), "r"(a2), "r"(a3), "r"(b0), "r"(b1));
}

__device__ __forceinline__ unsigned cvt_h2(float2 v) {
    __half2 h = __floats2half2_rn(v.x, v.y);
    return *(unsigned*)&h;
}

// ------------------------------------------------------------------
// one-shot weight prep: fp32 -> fp16 transposed images
// ------------------------------------------------------------------
__global__ void prep_w_k(const float* __restrict__ Wf,
                         const float* __restrict__ convW,
                         const float* __restrict__ linW) {
    int idx = blockIdx.x * 256 + threadIdx.x;
    if (idx < IN_F * HID) {                      // former1: Wf[k][n] -> [n][k]
        int k = idx >> 6, n = idx & 63;
        g_WtF[n][k] = __float2half(Wf[idx]);
    } else if (idx < IN_F * HID + NLAYER * HID * 128) {
        int t = idx - IN_F * HID;
        int l = t >> 13;
        int r = t & 8191;
        int k = r >> 7, j = r & 127;
        float w = (j < 64) ? convW[l * 4096 + k * 64 + j]
                           : linW[l * 4096 + k * 64 + (j - 64)];
        g_Wt2[l][j][k] = __float2half(w);
    }
}

// ------------------------------------------------------------------
// CSR build (unordered segments: starts assigned by atomic bump)
// ------------------------------------------------------------------
__global__ void count_deg_k(const int* __restrict__ ei) {
    if (blockIdx.x == 0 && threadIdx.x == 0) g_total = 0;
    int e0 = (blockIdx.x * 256 + threadIdx.x) * 4;
    if (e0 < EE) {
        int4 d4 = *(const int4*)&ei[EE + e0];
        atomicAdd(&g_cnt[d4.x], 1);
        atomicAdd(&g_cnt[d4.y], 1);
        atomicAdd(&g_cnt[d4.z], 1);
        atomicAdd(&g_cnt[d4.w], 1);
    }
}

__global__ void start_k() {
    int i = blockIdx.x * 256 + threadIdx.x;
    if (i < NN) {
        int c = g_cnt[i];
        g_dinv[i] = rsqrtf((float)c + 1.0f);
        int s = atomicAdd(&g_total, c);
        g_start[i] = s;
        g_fill[i]  = s;
    }
}

__global__ void fill_k(const int* __restrict__ ei) {
    int e0 = (blockIdx.x * 256 + threadIdx.x) * 4;
    if (e0 < EE) {
        int4 s4 = *(const int4*)&ei[e0];
        int4 d4 = *(const int4*)&ei[EE + e0];
        int p0 = atomicAdd(&g_fill[d4.x], 1);
        int p1 = atomicAdd(&g_fill[d4.y], 1);
        int p2 = atomicAdd(&g_fill[d4.z], 1);
        int p3 = atomicAdd(&g_fill[d4.w], 1);
        g_srcbuf[p0] = s4.x;
        g_srcbuf[p1] = s4.y;
        g_srcbuf[p2] = s4.z;
        g_srcbuf[p3] = s4.w;
    }
}

// ------------------------------------------------------------------
// former1 (mma): h = x @ Wf + bf   [N,128] @ [128,64]
// 128 threads / 4 warps; 64 rows/block
// A fragments loaded DIRECTLY from global x (float2 -> fp16 cvt in regs);
// no activation smem, no staging sync for x. Wt tile from g_WtF (reused).
// ------------------------------------------------------------------
__global__ void former1_mma(const float* __restrict__ x,
                            const float* __restrict__ bf) {
    __shared__ __half Wt[HID][IN_F + 8];
    __shared__ float  bs[HID];

    int tid  = threadIdx.x;
    int warp = tid >> 5, lane = tid & 31;
    int row0b = blockIdx.x * 64;

    // weight tile: vectorized copy (64*136 halfs = 1088 float4)
    {
        const float4* src = (const float4*)g_WtF;
        float4* dst = (float4*)Wt;
        for (int i = tid; i < (HID * (IN_F + 8)) / 8; i += 128) dst[i] = src[i];
    }
    if (tid < HID) bs[tid] = bf[tid];
    __syncthreads();

    int gr = lane >> 2, tg = lane & 3;
    int m0 = warp * 16;
    int r0g = min(row0b + m0 + gr, NN - 1);       // this lane's row (clamped)
    int r1g = min(row0b + m0 + gr + 8, NN - 1);
    const float* xr0 = &x[r0g * IN_F];
    const float* xr1 = &x[r1g * IN_F];

    float acc[8][4];
#pragma unroll
    for (int nf = 0; nf < 8; nf++)
#pragma unroll
        for (int j = 0; j < 4; j++) acc[nf][j] = 0.f;

#pragma unroll
    for (int ks = 0; ks < 8; ks++) {
        int ac = ks * 16 + tg * 2;
        unsigned a0 = cvt_h2(*(const float2*)&xr0[ac]);
        unsigned a1 = cvt_h2(*(const float2*)&xr1[ac]);
        unsigned a2 = cvt_h2(*(const float2*)&xr0[ac + 8]);
        unsigned a3 = cvt_h2(*(const float2*)&xr1[ac + 8]);
#pragma unroll
        for (int nf = 0; nf < 8; nf++) {
            unsigned b0 = *(const unsigned*)&Wt[nf * 8 + gr][ac];
            unsigned b1 = *(const unsigned*)&Wt[nf * 8 + gr][ac + 8];
            mma16816(acc[nf], a0, a1, a2, a3, b0, b1);
        }
    }

    int r0 = row0b + m0 + gr;
#pragma unroll
    for (int nf = 0; nf < 8; nf++) {
        int col = nf * 8 + tg * 2;
        if (r0 < NN) {
            float2 v = make_float2(acc[nf][0] + bs[col], acc[nf][1] + bs[col + 1]);
            *(float2*)&g_h[r0 * HID + col] = v;
        }
        if (r0 + 8 < NN) {
            float2 v = make_float2(acc[nf][2] + bs[col], acc[nf][3] + bs[col + 1]);
            *(float2*)&g_h[(r0 + 8) * HID + col] = v;
        }
    }
}

// ------------------------------------------------------------------
// layer GEMM (mma): D[64rows,128cols] = h @ [convW | linW]
//   cols 0-63  -> g_hws = fp16(dinv*D)    cols 64-127 -> g_r = D + bias
// A fragments loaded directly from g_h (L2-resident); Wt2 tile in smem
// ------------------------------------------------------------------
__global__ void layer_mma(const float* __restrict__ convB,
                          const float* __restrict__ linB,
                          int layer) {
    __shared__ __half Wt2[128][HID + 8];

    int tid  = threadIdx.x;
    int warp = tid >> 5, lane = tid & 31;
    int row0b = blockIdx.x * 64;

    // weight tile: vectorized copy (128*72 halfs = 1152 float4)
    {
        const float4* src = (const float4*)g_Wt2[layer];
        float4* dst = (float4*)Wt2;
        for (int i = tid; i < (128 * (HID + 8)) / 8; i += 128) dst[i] = src[i];
    }
    __syncthreads();

    int gr = lane >> 2, tg = lane & 3;
    int m0 = warp * 16;
    int r0g = min(row0b + m0 + gr, NN - 1);
    int r1g = min(row0b + m0 + gr + 8, NN - 1);
    const float* hr0 = &g_h[r0g * HID];
    const float* hr1 = &g_h[r1g * HID];

    float acc[16][4];
#pragma unroll
    for (int nf = 0; nf < 16; nf++)
#pragma unroll
        for (int j = 0; j < 4; j++) acc[nf][j] = 0.f;

#pragma unroll
    for (int ks = 0; ks < 4; ks++) {
        int ac = ks * 16 + tg * 2;
        unsigned a0 = cvt_h2(*(const float2*)&hr0[ac]);
        unsigned a1 = cvt_h2(*(const float2*)&hr1[ac]);
        unsigned a2 = cvt_h2(*(const float2*)&hr0[ac + 8]);
        unsigned a3 = cvt_h2(*(const float2*)&hr1[ac + 8]);
#pragma unroll
        for (int nf = 0; nf < 16; nf++) {
            unsigned b0 = *(const unsigned*)&Wt2[nf * 8 + gr][ac];
            unsigned b1 = *(const unsigned*)&Wt2[nf * 8 + gr][ac + 8];
            mma16816(acc[nf], a0, a1, a2, a3, b0, b1);
        }
    }

    int r0 = row0b + m0 + gr;
    int r1 = r0 + 8;
    bool ok0 = (r0 < NN), ok1 = (r1 < NN);
    float dv0 = ok0 ? g_dinv[r0] : 0.f;
    float dv1 = ok1 ? g_dinv[r1] : 0.f;
#pragma unroll
    for (int nf = 0; nf < 16; nf++) {
        int colc = nf * 8 + tg * 2;          // combined col
        if (colc < 64) {                     // conv branch -> fp16 hws
            if (ok0) {
                __half2 h = __floats2half2_rn(acc[nf][0] * dv0, acc[nf][1] * dv0);
                *(__half2*)&g_hws[r0 * HID + colc] = h;
            }
            if (ok1) {
                __half2 h = __floats2half2_rn(acc[nf][2] * dv1, acc[nf][3] * dv1);
                *(__half2*)&g_hws[r1 * HID + colc] = h;
            }
        } else {                             // residual branch -> fp32 r
            int col = colc - 64;
            float b0 = __ldg(&convB[col])     + __ldg(&linB[col]);
            float b1 = __ldg(&convB[col + 1]) + __ldg(&linB[col + 1]);
            if (ok0) {
                float2 v = make_float2(acc[nf][0] + b0, acc[nf][1] + b1);
                *(float2*)&g_r[r0 * HID + col] = v;
            }
            if (ok1) {
                float2 v = make_float2(acc[nf][2] + b0, acc[nf][3] + b1);
                *(float2*)&g_r[r1 * HID + col] = v;
            }
        }
    }
}

// ------------------------------------------------------------------
// aggregation: h = relu(BN( dn*(sum_e hws[src] + hws[node]) + r[node] ))
// warp per node, half2 gather per lane, 8-deep independent gather chains
// ------------------------------------------------------------------
__global__ void agg_k(const float* __restrict__ gamma,
                      const float* __restrict__ beta,
                      const float* __restrict__ mean,
                      const float* __restrict__ var) {
    int warp = threadIdx.x >> 5;
    int lane = threadIdx.x & 31;
    int node = blockIdx.x * 8 + warp;
    if (node >= NN) return;

    int c = lane * 2;
    float dn  = g_dinv[node];
    int   beg = g_start[node];
    int   end = beg + g_cnt[node];

    const __half2* hws = (const __half2*)g_hws;
    float2 a = __half22float2(hws[node * 32 + lane]);   // self term

    int i = beg;
    for (; i + 8 <= end; i += 8) {
        int s[8];
#pragma unroll
        for (int j = 0; j < 8; j++) s[j] = __ldg(&g_srcbuf[i + j]);
        float2 v[8];
#pragma unroll
        for (int j = 0; j < 8; j++)
            v[j] = __half22float2(__ldg(&hws[s[j] * 32 + lane]));
        float2 t0, t1, t2, t3;
        t0.x = v[0].x + v[1].x; t0.y = v[0].y + v[1].y;
        t1.x = v[2].x + v[3].x; t1.y = v[2].y + v[3].y;
        t2.x = v[4].x + v[5].x; t2.y = v[4].y + v[5].y;
        t3.x = v[6].x + v[7].x; t3.y = v[6].y + v[7].y;
        a.x += (t0.x + t1.x) + (t2.x + t3.x);
        a.y += (t0.y + t1.y) + (t2.y + t3.y);
    }
    for (; i < end; i++) {
        int s = __ldg(&g_srcbuf[i]);
        float2 v = __half22float2(__ldg(&hws[s * 32 + lane]));
        a.x += v.x;
        a.y += v.y;
    }

    float2 rr = ((const float2*)g_r)[node * 32 + lane];
    a.x = a.x * dn + rr.x;
    a.y = a.y * dn + rr.y;

    float s0 = gamma[c]     * rsqrtf(var[c]     + 1e-5f);
    float s1 = gamma[c + 1] * rsqrtf(var[c + 1] + 1e-5f);
    float2 o;
    o.x = fmaxf((a.x - mean[c])     * s0 + beta[c],     0.f);
    o.y = fmaxf((a.y - mean[c + 1]) * s1 + beta[c + 1], 0.f);
    ((float2*)g_h)[node * 32 + lane] = o;
}

// ------------------------------------------------------------------
// pred head: out = h @ predW + predB   [N,64] @ [64,40]
// ------------------------------------------------------------------
__global__ void pred_k(const float* __restrict__ Wp,
                       const float* __restrict__ bp,
                       float* __restrict__ out) {
    __shared__ float Ws[HID * OUT_F];
    __shared__ float bs[OUT_F];
    int tid = threadIdx.x;
    for (int idx = tid; idx < HID * OUT_F; idx += 256) Ws[idx] = Wp[idx];
    if (tid < OUT_F) bs[tid] = bp[tid];
    __syncthreads();
    if (tid >= 240) return;

    int col  = tid % OUT_F;
    int grp  = tid / OUT_F;
    int row0 = blockIdx.x * 24 + grp * 4;
    int r[4];
#pragma unroll
    for (int rr = 0; rr < 4; rr++) r[rr] = min(row0 + rr, NN - 1);

    float acc[4] = {};
    for (int k = 0; k < HID; k += 4) {
        float4 hv[4];
#pragma unroll
        for (int rr = 0; rr < 4; rr++)
            hv[rr] = *(const float4*)&g_h[r[rr] * HID + k];
#pragma unroll
        for (int kk = 0; kk < 4; kk++) {
            float w = Ws[(k + kk) * OUT_F + col];
#pragma unroll
            for (int rr = 0; rr < 4; rr++) {
                float xs = (kk == 0) ? hv[rr].x : (kk == 1) ? hv[rr].y
                         : (kk == 2) ? hv[rr].z : hv[rr].w;
                acc[rr] += xs * w;
            }
        }
    }
#pragma unroll
    for (int rr = 0; rr < 4; rr++) {
        int row = row0 + rr;
        if (row < NN) out[row * OUT_F + col] = acc[rr] + bs[col];
    }
}

// ------------------------------------------------------------------
extern "C" void kernel_launch(void* const* d_in, const int* in_sizes, int n_in,
                              void* d_out, int out_size) {
    const float* x     = (const float*)d_in[0];
    const int*   ei    = (const int*)  d_in[1];
    const float* Wf    = (const float*)d_in[2];
    const float* bf    = (const float*)d_in[3];
    const float* convW = (const float*)d_in[4];
    const float* convB = (const float*)d_in[5];
    const float* linW  = (const float*)d_in[6];
    const float* linB  = (const float*)d_in[7];
    const float* gamma = (const float*)d_in[8];
    const float* beta  = (const float*)d_in[9];
    const float* rmean = (const float*)d_in[10];
    const float* rvar  = (const float*)d_in[11];
    const float* predW = (const float*)d_in[12];
    const float* predB = (const float*)d_in[13];
    float* out = (float*)d_out;

    void* cnt_ptr = nullptr;
    cudaGetSymbolAddress(&cnt_ptr, g_cnt);
    cudaMemsetAsync(cnt_ptr, 0, NN * sizeof(int), 0);

    prep_w_k <<<(IN_F * HID + NLAYER * HID * 128 + 255) / 256, 256>>>(Wf, convW, linW);

    count_deg_k <<<(EE / 4 + 255) / 256, 256>>>(ei);
    start_k     <<<(NN + 255) / 256, 256>>>();
    fill_k      <<<(EE / 4 + 255) / 256, 256>>>(ei);

    former1_mma<<<(NN + 63) / 64, 128>>>(x, bf);

    for (int l = 0; l < NLAYER; l++) {
        layer_mma<<<(NN + 63) / 64, 128>>>(convB + l * HID, linB + l * HID, l);
        agg_k<<<(NN + 7) / 8, 256>>>(
            gamma + l * HID, beta + l * HID,
            rmean + l * HID, rvar + l * HID);
    }

    pred_k<<<(NN + 23) / 24, 256>>>(predW, predB, out);
}